// round 8
// baseline (speedup 1.0000x reference)
#include <cuda_runtime.h>
#include <cstdint>

#define NQ    32
#define KCB   1024
#define CDIM  8
#define DDIM  1024
#define BDIMS 8
#define TDIM  4096
#define TILE  32
#define NTH   512
#define NCOLS (BDIMS*TDIM)          /* 32768 */
#define BDT   (BDIMS*DDIM*TDIM)     /* 33554432 */
#define NQBT  (NQ*NCOLS)            /* 1048576 */

/* shared memory offsets (floats) */
#define SM_R    0                   /* 1024 x 32 residual, swizzled float4  */
#define SM_W    32768               /* 8 x 1024 : iw (P1) then owT (P3)     */
#define SM_OB   40960               /* 1024                                 */
#define SM_CBT  41984               /* cbT: 8 x 1024                        */
#define SM_C2   50176               /* 1024                                 */
#define SM_ZE   51200               /* 32 x 9                               */
#define SM_PART 51488               /* 16 w x 16 ull = 512 floats           */
#define SM_ZQP  52000               /* (8tg x 2tp x 8c) ull = 256 floats    */
#define SM_M    52256               /* 32                                   */
#define SM_MP   52288               /* 16 ull = 32 floats                   */
#define SM_BD   52320               /* 16 x 32                              */
#define SM_BK   52832               /* 16 x 32                              */
#define SM_IB   53344               /* 8                                    */
#define SM_TOT  53352
#define SM_BYTES (SM_TOT*4)

typedef unsigned long long ull;

__device__ float g_owT[NQ * CDIM * DDIM];   /* [q][c][d] */
__device__ float g_cbT[NQ * CDIM * KCB];    /* [q][c][k] */
__device__ float g_c2 [NQ * KCB];           /* |cb|^2    */

__device__ __forceinline__ ull f2x(float lo, float hi) {
    ull r;
    asm("mov.b64 %0, {%1, %2};" : "=l"(r)
        : "r"(__float_as_uint(lo)), "r"(__float_as_uint(hi)));
    return r;
}
__device__ __forceinline__ void upk(ull v, float& lo, float& hi) {
    unsigned a, b;
    asm("mov.b64 {%0, %1}, %2;" : "=r"(a), "=r"(b) : "l"(v));
    lo = __uint_as_float(a); hi = __uint_as_float(b);
}
#define FMA2(D,A,B,C) asm("fma.rn.f32x2 %0, %1, %2, %3;" : "=l"(D) : "l"(A), "l"(B), "l"(C))
#define ADD2(D,A,B)   asm("add.rn.f32x2 %0, %1, %2;"     : "=l"(D) : "l"(A), "l"(B))

__global__ void prep_kernel(const float* __restrict__ ow,
                            const float* __restrict__ cb)
{
    int idx = blockIdx.x * blockDim.x + threadIdx.x;
    int stride = gridDim.x * blockDim.x;
    for (int i = idx; i < NQ * CDIM * DDIM; i += stride) {
        int q = i >> 13, r = i & 8191, c = r >> 10, d = r & 1023;
        g_owT[i] = ow[(q << 13) + (d << 3) + c];
    }
    for (int i = idx; i < NQ * CDIM * KCB; i += stride) {
        int q = i >> 13, r = i & 8191, c = r >> 10, k = r & 1023;
        g_cbT[i] = cb[(q << 13) + (k << 3) + c];
    }
    for (int k = idx; k < NQ * KCB; k += stride) {
        const float4* row = (const float4*)(cb + (size_t)k * 8);
        float4 a = row[0], b4 = row[1];
        float p = fmaf(a.x, a.x, fmaf(a.y, a.y, fmaf(a.z, a.z, a.w * a.w)));
        float o = fmaf(b4.x, b4.x, fmaf(b4.y, b4.y, fmaf(b4.z, b4.z, b4.w * b4.w)));
        g_c2[k] = p + o;
    }
}

__global__ __launch_bounds__(NTH, 1)
void rvq_kernel(const float* __restrict__ z,
                const float* __restrict__ iw,
                const float* __restrict__ ibias,
                const float* __restrict__ obias,
                const float* __restrict__ cb,
                const int*   __restrict__ inlen,
                float* __restrict__ out,
                int wout, int widx, int wlen)
{
    extern __shared__ float sm[];
    float* r_s   = sm + SM_R;
    float* w_s   = sm + SM_W;
    float* ob_s  = sm + SM_OB;
    float* cbt_s = sm + SM_CBT;
    float* c2_s  = sm + SM_C2;
    float* ze_s  = sm + SM_ZE;
    ull*   partu = (ull*)(sm + SM_PART);
    float* partf = sm + SM_PART;
    ull*   zqp_u = (ull*)(sm + SM_ZQP);
    float* zqp_f = sm + SM_ZQP;
    float* m_s   = sm + SM_M;
    ull*   mp_u  = (ull*)(sm + SM_MP);
    float* mp_f  = sm + SM_MP;
    float* bd_s  = sm + SM_BD;
    int*   bk_s  = (int*)(sm + SM_BK);
    float* ib_s  = sm + SM_IB;
    float4* R4   = (float4*)r_s;

    const int tid  = threadIdx.x;
    const int lane = tid & 31;
    const int w    = tid >> 5;          /* 0..15 */
    const int tg   = w >> 1;            /* 0..7 : 4-t quad */
    const int dg   = w & 1;             /* 0..1 : 512-d slice */

    const int col0 = blockIdx.x * TILE;
    const int b    = col0 >> 12;
    const int t0   = col0 & (TDIM - 1);
    const int len  = inlen[b];

    const float* zb = z + (size_t)b * DDIM * TDIM + t0;

    if (tid < TILE) {
        int t = tid;
        float m = ((t0 + t) < len) ? 1.0f : 0.0f;
        m_s[t] = m;
        int tgg = t >> 2, tj = t & 3, tp = tj >> 1, h = tj & 1;
        mp_f[(tgg * 2 + tp) * 2 + h] = -m;
    }

    /* ---- init residual = z * mask (swizzled float4 over t-quads) ---- */
    #pragma unroll
    for (int it = 0; it < 16; it++) {
        int i = tid + it * NTH;
        int d = i >> 3, tq = i & 7;
        float4 v = *(const float4*)(zb + (size_t)d * TDIM + (tq << 2));
        int tb = t0 + (tq << 2);
        v.x = (tb + 0 < len) ? v.x : 0.0f;
        v.y = (tb + 1 < len) ? v.y : 0.0f;
        v.z = (tb + 2 < len) ? v.z : 0.0f;
        v.w = (tb + 3 < len) ? v.w : 0.0f;
        R4[d * 8 + (tq ^ (d & 7))] = v;
    }
    __syncthreads();

    for (int q = 0; q < NQ; q++) {
        /* ---- stage A: iw -> w_s, cbT -> cbt_s, c2, ob, ib ---- */
        {
            const float4* iw4 = (const float4*)(iw + (size_t)q * CDIM * DDIM);
            float4* w4 = (float4*)w_s;
            #pragma unroll
            for (int it = 0; it < 4; it++) w4[tid + it * NTH] = iw4[tid + it * NTH];

            const float4* cbt4 = (const float4*)(g_cbT + (size_t)q * CDIM * KCB);
            float4* cs4 = (float4*)cbt_s;
            #pragma unroll
            for (int it = 0; it < 4; it++) cs4[tid + it * NTH] = cbt4[tid + it * NTH];

            if (tid < 256) {
                ((float4*)c2_s)[tid] = ((const float4*)(g_c2 + (size_t)q * KCB))[tid];
                ((float4*)ob_s)[tid] = ((const float4*)(obias + (size_t)q * DDIM))[tid];
            }
            if (tid < CDIM) ib_s[tid] = ibias[q * CDIM + tid];
        }
        __syncthreads();

        /* ====== phase 1 (packed): v[tp*8+c] over warp's 512-d slice ====== */
        {
            ull v[16];
            #pragma unroll
            for (int i = 0; i < 16; i++) v[i] = 0ull;

            #pragma unroll 4
            for (int i = 0; i < 16; i++) {
                int d = dg * 512 + lane + (i << 5);
                ulonglong2 r = *(const ulonglong2*)&R4[d * 8 + (tg ^ (d & 7))];
                #pragma unroll
                for (int c = 0; c < 8; c++) {
                    float wv = w_s[c * 1024 + d];
                    ull wd = f2x(wv, wv);
                    FMA2(v[c],     wd, r.x, v[c]);      /* tp=0: t0,t1 */
                    FMA2(v[8 + c], wd, r.y, v[8 + c]);  /* tp=1: t2,t3 */
                }
            }
            /* split-exchange reduction: 16 ull over 32 lanes */
            int n = 16;
            #pragma unroll
            for (int off = 16; off >= 2; off >>= 1) {
                n >>= 1;
                bool hi = (lane & off) != 0;
                #pragma unroll
                for (int i = 0; i < 8; i++) {
                    if (i < n) {
                        ull send = hi ? v[i] : v[i + n];
                        ull recv = __shfl_xor_sync(0xffffffffu, send, off);
                        ull keep = hi ? v[i + n] : v[i];
                        ADD2(v[i], keep, recv);
                    }
                }
            }
            {
                ull o = __shfl_xor_sync(0xffffffffu, v[0], 1);
                ADD2(v[0], v[0], o);
            }
            /* lane pair (l, l^1) holds idx = bit3<-lane4, bits2..0<-lane3..1 */
            if ((lane & 1) == 0) {
                int idx = ((lane & 16) >> 1) | ((lane >> 1) & 7);
                partu[w * 16 + idx] = v[0];
            }
        }
        __syncthreads();

        /* ---- combine dg partials -> ze ; stage B: owT -> w_s ---- */
        if (tid < 256) {
            int t = tid >> 3, c = tid & 7;
            int tgg = t >> 2, tj = t & 3, tp = tj >> 1, h = tj & 1;
            float s = partf[(((tgg * 2 + 0) * 16) + tp * 8 + c) * 2 + h]
                    + partf[(((tgg * 2 + 1) * 16) + tp * 8 + c) * 2 + h]
                    + ib_s[c];
            ze_s[t * 9 + c] = s;
        }
        {
            const float4* owT4 = (const float4*)(g_owT + (size_t)q * CDIM * DDIM);
            float4* w4 = (float4*)w_s;
            #pragma unroll
            for (int it = 0; it < 4; it++) w4[tid + it * NTH] = owT4[tid + it * NTH];
        }
        __syncthreads();

        /* ====== phase 2 (packed k-quads): lane = t, warp = 64 k's ====== */
        {
            int t = lane;
            ull ed[8];
            #pragma unroll
            for (int c = 0; c < 8; c++) {
                float e = ze_s[t * 9 + c];
                ed[c] = f2x(e, e);
            }
            const ull n2 = f2x(-2.0f, -2.0f);
            float best = 3.402823466e38f;
            int bk = 0;
            const int kb = w << 6;
            #pragma unroll 4
            for (int i = 0; i < 16; i++) {
                int k = kb + (i << 2);
                ull sA = 0ull, sB = 0ull;
                #pragma unroll
                for (int c = 0; c < 8; c++) {
                    ulonglong2 cv = *(const ulonglong2*)(cbt_s + c * 1024 + k);
                    FMA2(sA, cv.x, ed[c], sA);
                    FMA2(sB, cv.y, ed[c], sB);
                }
                ulonglong2 c2v = *(const ulonglong2*)(c2_s + k);
                ull bA, bB;
                FMA2(bA, sA, n2, c2v.x);   /* dist = c2 - 2s (e2 rank-invariant) */
                FMA2(bB, sB, n2, c2v.y);
                float da, db, dc, dd;
                upk(bA, da, db); upk(bB, dc, dd);
                if (da < best) { best = da; bk = k;     }
                if (db < best) { best = db; bk = k + 1; }
                if (dc < best) { best = dc; bk = k + 2; }
                if (dd < best) { best = dd; bk = k + 3; }
            }
            bd_s[w * 32 + t] = best;
            bk_s[w * 32 + t] = bk;
        }
        __syncthreads();

        /* ====== final argmin over 16 k-chunks + stage -zq*m (paired) ==== */
        if (tid < TILE) {
            int t = tid;
            float best = bd_s[t];
            int bk = bk_s[t];
            #pragma unroll
            for (int kc = 1; kc < 16; kc++) {
                float d2 = bd_s[kc * 32 + t];
                if (d2 < best) { best = d2; bk = bk_s[kc * 32 + t]; }
            }
            if (widx) out[BDT + q * NCOLS + col0 + t] = (float)bk;
            float mt = m_s[t];
            const float4* cr = (const float4*)(cb + (((size_t)q << 10) + bk) * 8);
            float4 ca = cr[0], cb4 = cr[1];
            int tgg = t >> 2, tj = t & 3, tp = tj >> 1, h = tj & 1;
            float* zp = zqp_f + ((tgg * 2 + tp) * 8) * 2 + h;
            zp[0]  = -ca.x * mt;  zp[2]  = -ca.y * mt;
            zp[4]  = -ca.z * mt;  zp[6]  = -ca.w * mt;
            zp[8]  = -cb4.x * mt; zp[10] = -cb4.y * mt;
            zp[12] = -cb4.z * mt; zp[14] = -cb4.w * mt;
        }
        __syncthreads();

        /* ====== phase 3 (packed): r -= ow.zq + ob*m over 512-d slice ==== */
        {
            ull zqA[8], zqB[8];
            #pragma unroll
            for (int c = 0; c < 8; c++) {
                zqA[c] = zqp_u[(tg * 2 + 0) * 8 + c];
                zqB[c] = zqp_u[(tg * 2 + 1) * 8 + c];
            }
            const ull nmA = mp_u[tg * 2 + 0];
            const ull nmB = mp_u[tg * 2 + 1];
            #pragma unroll 4
            for (int i = 0; i < 16; i++) {
                int d = dg * 512 + lane + (i << 5);
                int slot = d * 8 + (tg ^ (d & 7));
                ulonglong2 r = *(const ulonglong2*)&R4[slot];
                float obv = ob_s[d];
                ull obd2 = f2x(obv, obv);
                FMA2(r.x, obd2, nmA, r.x);
                FMA2(r.y, obd2, nmB, r.y);
                #pragma unroll
                for (int c = 0; c < 8; c++) {
                    float wv = w_s[c * 1024 + d];
                    ull wd = f2x(wv, wv);
                    FMA2(r.x, wd, zqA[c], r.x);
                    FMA2(r.y, wd, zqB[c], r.y);
                }
                *(ulonglong2*)&R4[slot] = r;
            }
        }
        __syncthreads();
    }

    /* ---- epilogue: qout = z*mask - r_final ---- */
    if (wout) {
        #pragma unroll
        for (int it = 0; it < 16; it++) {
            int i = tid + it * NTH;
            int d = i >> 3, tq = i & 7;
            float4 zv = *(const float4*)(zb + (size_t)d * TDIM + (tq << 2));
            float4 rv = R4[d * 8 + (tq ^ (d & 7))];
            int tb = t0 + (tq << 2);
            float4 o;
            o.x = ((tb + 0 < len) ? zv.x : 0.0f) - rv.x;
            o.y = ((tb + 1 < len) ? zv.y : 0.0f) - rv.y;
            o.z = ((tb + 2 < len) ? zv.z : 0.0f) - rv.z;
            o.w = ((tb + 3 < len) ? zv.w : 0.0f) - rv.w;
            *(float4*)(out + (size_t)b * DDIM * TDIM + (size_t)d * TDIM + t0 + (tq << 2)) = o;
        }
    }
    if (wlen && blockIdx.x == 0 && tid < BDIMS)
        out[BDT + NQBT + tid] = (float)inlen[tid];
}

extern "C" void kernel_launch(void* const* d_in, const int* in_sizes, int n_in,
                              void* d_out, int out_size)
{
    const float* z   = (const float*)d_in[0];
    const float* iw  = (const float*)d_in[1];
    const float* ib  = (const float*)d_in[2];
    const float* ow  = (const float*)d_in[3];
    const float* ob  = (const float*)d_in[4];
    const float* cbk = (const float*)d_in[5];
    const int* inlen = (const int*)d_in[6];
    float* out = (float*)d_out;

    cudaFuncSetAttribute(rvq_kernel, cudaFuncAttributeMaxDynamicSharedMemorySize, SM_BYTES);

    int wout = (out_size >= BDT) ? 1 : 0;
    int widx = (out_size >= BDT + NQBT) ? 1 : 0;
    int wlen = (out_size >= BDT + NQBT + BDIMS) ? 1 : 0;

    prep_kernel<<<256, 512>>>(ow, cbk);
    rvq_kernel<<<NCOLS / TILE, NTH, SM_BYTES>>>(z, iw, ib, ob, cbk, inlen,
                                               out, wout, widx, wlen);
}